// round 2
// baseline (speedup 1.0000x reference)
#include <cuda_runtime.h>

#define BB 16384
#define HH 50
#define DD 64
#define N_ITEMS 100000
#define NB 5          // batch rows per CTA
#define NTHR 256

// Precomputed P[item][d] = sum_k i2e[item][k] * w_r1[d][k]   (25.6 MB, L2-resident)
__device__ float g_P[N_ITEMS * DD];

// ---------------- smem layout (floats) ----------------
#define OFF_WR2    0        // 4096   w_r2 [d*64+k]
#define OFF_ATT1A  4096     // 4096   att1[:, :64]
#define OFF_ATT2   8192     // 4096
#define OFF_LIN1B  12288    // 64*65  lin1[:, 64:] padded [d*65+k]
#define OFF_ATT3   16448    // 64
#define OFF_B2     16512    // 64
#define OFF_ATT2B  16576    // 64
#define OFF_MISC   16640    // 16  ([0]=att3_b)
#define OFF_RPROJ  16656    // 5*68 padded [r*68+d]
#define OFF_U      16996    // 5*64
#define OFF_UATT   17316    // 5*64
#define OFF_ULIN   17636    // 5*64
#define OFF_LOGIT  17956    // 256
#define OFF_P      18212    // 256
#define OFF_RED    18468    // 16 (m[0..7], inv[8..15])
#define OFF_NEIGH  18484    // 5*64 (=18804)
#define OFF_O      18816    // 250*65 = 16250  (also preamble scratch)
#define SMEM_FLOATS 35072
#define SMEM_BYTES  (SMEM_FLOATS * 4)

// GEMV: OUT[64] = relu(W[64x64] @ IN[64] + BIASARR[d]), IN/OUT registers.
// W in smem read as broadcast LDS.128 (1 wavefront per 4 FFMA).
#define GEMV64(OUT, IN, W, BIASARR, BIASSTEP) do {                      \
    _Pragma("unroll")                                                   \
    for (int d0_ = 0; d0_ < 64; d0_ += 8) {                             \
      float acc_[8];                                                    \
      _Pragma("unroll")                                                 \
      for (int i_ = 0; i_ < 8; i_++)                                    \
        acc_[i_] = (BIASARR)[(d0_ + i_) * (BIASSTEP)];                  \
      _Pragma("unroll")                                                 \
      for (int k_ = 0; k_ < 64; k_ += 4) {                              \
        _Pragma("unroll")                                               \
        for (int i_ = 0; i_ < 8; i_++) {                                \
          float4 w_ = *(const float4*)&(W)[(d0_ + i_) * 64 + k_];       \
          acc_[i_] = fmaf((IN)[k_ + 0], w_.x, acc_[i_]);                \
          acc_[i_] = fmaf((IN)[k_ + 1], w_.y, acc_[i_]);                \
          acc_[i_] = fmaf((IN)[k_ + 2], w_.z, acc_[i_]);                \
          acc_[i_] = fmaf((IN)[k_ + 3], w_.w, acc_[i_]);                \
        }                                                               \
      }                                                                 \
      _Pragma("unroll")                                                 \
      for (int i_ = 0; i_ < 8; i_++)                                    \
        (OUT)[d0_ + i_] = fmaxf(acc_[i_], 0.0f);                        \
    }                                                                   \
  } while (0)

// ---------------- P precompute: P = i2e @ W_r1a^T ----------------
__global__ __launch_bounds__(256) void precompute_P_kernel(
    const float* __restrict__ i2e, const float* __restrict__ wr1) {
  __shared__ float e_s[64 * 68];   // item rows, padded
  __shared__ float wt[64 * 68];    // wt[k*68+d] = wr1[d*128+k]
  const int tid = threadIdx.x;
  const int base = blockIdx.x * 64;

  for (int i = tid; i < 64 * 64; i += 256) {
    int it = i >> 6, k = i & 63;
    int item = base + it;
    e_s[it * 68 + k] = (item < N_ITEMS) ? i2e[(long)item * 64 + k] : 0.0f;
  }
  for (int i = tid; i < 64 * 64; i += 256) {
    int d = i >> 6, k = i & 63;
    wt[k * 68 + d] = wr1[d * 128 + k];
  }
  __syncthreads();

  const int il = tid >> 3;   // 0..31
  const int dq = tid & 7;    // 0..7  -> outputs d = dq*8 .. dq*8+7
  for (int sb = 0; sb < 2; sb++) {
    int it = sb * 32 + il;
    int item = base + it;
    float acc[8];
#pragma unroll
    for (int i = 0; i < 8; i++) acc[i] = 0.0f;
#pragma unroll
    for (int k = 0; k < 64; k++) {
      float ev = e_s[it * 68 + k];
      float4 w0 = *(const float4*)&wt[k * 68 + dq * 8];
      float4 w1 = *(const float4*)&wt[k * 68 + dq * 8 + 4];
      acc[0] = fmaf(ev, w0.x, acc[0]); acc[1] = fmaf(ev, w0.y, acc[1]);
      acc[2] = fmaf(ev, w0.z, acc[2]); acc[3] = fmaf(ev, w0.w, acc[3]);
      acc[4] = fmaf(ev, w1.x, acc[4]); acc[5] = fmaf(ev, w1.y, acc[5]);
      acc[6] = fmaf(ev, w1.z, acc[6]); acc[7] = fmaf(ev, w1.w, acc[7]);
    }
    if (item < N_ITEMS) {
      float4* dst = (float4*)&g_P[(long)item * 64 + dq * 8];
      dst[0] = make_float4(acc[0], acc[1], acc[2], acc[3]);
      dst[1] = make_float4(acc[4], acc[5], acc[6], acc[7]);
    }
  }
}

// ---------------- fused main kernel ----------------
__global__ __launch_bounds__(NTHR, 1)
void ui_aggregator_main_kernel(
    const int* __restrict__ nodes, const int* __restrict__ hui,
    const int* __restrict__ hr, const float* __restrict__ u2e,
    const float* __restrict__ r2e,
    const float* __restrict__ wr1, const float* __restrict__ wr1b_,
    const float* __restrict__ wr2, const float* __restrict__ wr2b_,
    const float* __restrict__ att1, const float* __restrict__ att1b_,
    const float* __restrict__ att2w, const float* __restrict__ att2b_,
    const float* __restrict__ att3w, const float* __restrict__ att3b_,
    const float* __restrict__ lin1, const float* __restrict__ lin1b_,
    float* __restrict__ out) {
  extern __shared__ float sm[];
  const int tid = threadIdx.x;
  const int b0 = blockIdx.x * NB;
  const int nb = min(NB, BB - b0);

  float* s_wr2   = sm + OFF_WR2;
  float* s_att1a = sm + OFF_ATT1A;
  float* s_att2  = sm + OFF_ATT2;
  float* s_lin1b = sm + OFF_LIN1B;
  float* s_att3  = sm + OFF_ATT3;
  float* s_b2    = sm + OFF_B2;
  float* s_att2b = sm + OFF_ATT2B;
  float* s_misc  = sm + OFF_MISC;
  float* s_rproj = sm + OFF_RPROJ;
  float* s_u     = sm + OFF_U;
  float* s_uatt  = sm + OFF_UATT;
  float* s_ulin  = sm + OFF_ULIN;
  float* s_logit = sm + OFF_LOGIT;
  float* s_p     = sm + OFF_P;
  float* s_red   = sm + OFF_RED;
  float* s_neigh = sm + OFF_NEIGH;
  float* s_o     = sm + OFF_O;          // [e*65 + d]
  float* sc_a1bh = s_o;                 // preamble scratch, padded [d*65+k]
  float* sc_l1a  = s_o + 4160;
  float* sc_w1b  = s_o + 8320;

  // ---- preamble: stage weights ----
#pragma unroll 1
  for (int i = tid; i < 4096; i += NTHR) {
    int d = i >> 6, k = i & 63;
    s_wr2[i]   = wr2[i];
    s_att2[i]  = att2w[i];
    s_att1a[i] = att1[d * 128 + k];
    s_lin1b[d * 65 + k] = lin1[d * 128 + 64 + k];
    sc_a1bh[d * 65 + k] = att1[d * 128 + 64 + k];
    sc_l1a[d * 65 + k]  = lin1[d * 128 + k];
    sc_w1b[d * 65 + k]  = wr1[d * 128 + 64 + k];
  }
  if (tid < 64) {
    s_att3[tid]  = att3w[tid];
    s_b2[tid]    = wr2b_[tid];
    s_att2b[tid] = att2b_[tid];
  }
  if (tid == 0) s_misc[0] = att3b_[0];
  for (int i = tid; i < nb * 64; i += NTHR) {
    int bl = i >> 6;
    s_u[i] = u2e[(long)nodes[b0 + bl] * 64 + (i & 63)];
  }
  __syncthreads();

  // r_proj[r][d] = W_r1b @ r2e[r] + b1   (tiny: 5 ratings)
  for (int oi = tid; oi < 5 * 64; oi += NTHR) {
    int r = oi >> 6, d = oi & 63;
    float acc = wr1b_[d];
#pragma unroll
    for (int k = 0; k < 64; k++) acc = fmaf(sc_w1b[d * 65 + k], r2e[r * 64 + k], acc);
    s_rproj[r * 68 + d] = acc;
  }
  // uatt[b] = att1[:,64:] @ u + att1_b ; ulin[b] = lin1[:,:64] @ u + lin1_b
  for (int oi = tid; oi < nb * 128; oi += NTHR) {
    int bl = oi >> 7, j = oi & 127;
    const float* uu = &s_u[bl * 64];
    if (j < 64) {
      float acc = att1b_[j];
#pragma unroll
      for (int k = 0; k < 64; k++) acc = fmaf(sc_a1bh[j * 65 + k], uu[k], acc);
      s_uatt[bl * 64 + j] = acc;
    } else {
      int d = j - 64;
      float acc = lin1b_[d];
#pragma unroll
      for (int k = 0; k < 64; k++) acc = fmaf(sc_l1a[d * 65 + k], uu[k], acc);
      s_ulin[bl * 64 + d] = acc;
    }
  }
  __syncthreads();   // scratch region now free -> reused as s_o

  // ---- edge phase: one edge per thread ----
  const int e = tid;
  const int ne = nb * HH;
  if (e < ne) {
    int bl = e / HH;
    int gidx = (b0 + bl) * HH + (e - bl * HH);
    int item = hui[gidx];
    int r = hr[gidx];

    // h = relu(P[item] + r_proj[r])
    float v[64];
    const float4* Pp  = (const float4*)&g_P[(long)item * 64];
    const float4* rp4 = (const float4*)&s_rproj[r * 68];
#pragma unroll
    for (int i = 0; i < 16; i++) {
      float4 p = Pp[i];
      float4 q = rp4[i];
      v[4 * i + 0] = fmaxf(p.x + q.x, 0.0f);
      v[4 * i + 1] = fmaxf(p.y + q.y, 0.0f);
      v[4 * i + 2] = fmaxf(p.z + q.z, 0.0f);
      v[4 * i + 3] = fmaxf(p.w + q.w, 0.0f);
    }

    // o = relu(W_r2 @ h + b2)
    float o[64];
    GEMV64(o, v, s_wr2, s_b2, 1);
#pragma unroll
    for (int d = 0; d < 64; d++) s_o[e * 65 + d] = o[d];

    // a1 = relu(att1[:, :64] @ o + uatt[b])
    float a1[64];
    GEMV64(a1, o, s_att1a, (&s_uatt[bl * 64]), 1);

    // a2 = relu(att2 @ a1 + b), fused with the att3 logit dot
    float lg = s_misc[0];
#pragma unroll
    for (int d0 = 0; d0 < 64; d0 += 8) {
      float acc[8];
#pragma unroll
      for (int i = 0; i < 8; i++) acc[i] = s_att2b[d0 + i];
#pragma unroll
      for (int k = 0; k < 64; k += 4) {
#pragma unroll
        for (int i = 0; i < 8; i++) {
          float4 w = *(const float4*)&s_att2[(d0 + i) * 64 + k];
          acc[i] = fmaf(a1[k + 0], w.x, acc[i]);
          acc[i] = fmaf(a1[k + 1], w.y, acc[i]);
          acc[i] = fmaf(a1[k + 2], w.z, acc[i]);
          acc[i] = fmaf(a1[k + 3], w.w, acc[i]);
        }
      }
#pragma unroll
      for (int i = 0; i < 8; i++)
        lg = fmaf(s_att3[d0 + i], fmaxf(acc[i], 0.0f), lg);
    }
    s_logit[e] = lg;
  }
  __syncthreads();

  // ---- softmax over H per batch row ----
  if (tid < nb) {
    float m = -1e30f;
#pragma unroll 1
    for (int h = 0; h < HH; h++) m = fmaxf(m, s_logit[tid * HH + h]);
    s_red[tid] = m;
  }
  __syncthreads();
  if (e < ne) {
    int bl = e / HH;
    s_p[e] = __expf(s_logit[e] - s_red[bl]);
  }
  __syncthreads();
  if (tid < nb) {
    float s = 0.0f;
#pragma unroll 1
    for (int h = 0; h < HH; h++) s += s_p[tid * HH + h];
    s_red[8 + tid] = 1.0f / s;
  }
  __syncthreads();

  // ---- neigh[b][d] = sum_h p*o / sum ----
  for (int oi = tid; oi < nb * 64; oi += NTHR) {
    int bl = oi >> 6, d = oi & 63;
    float acc = 0.0f;
#pragma unroll 1
    for (int h = 0; h < HH; h++)
      acc = fmaf(s_p[bl * HH + h], s_o[(bl * HH + h) * 65 + d], acc);
    s_neigh[oi] = acc * s_red[8 + bl];
  }
  __syncthreads();

  // ---- out = relu(ulin + lin1[:, 64:] @ neigh) ----
  for (int oi = tid; oi < nb * 64; oi += NTHR) {
    int bl = oi >> 6, d = oi & 63;
    float acc = s_ulin[oi];
    const float* ng = &s_neigh[bl * 64];
#pragma unroll
    for (int k = 0; k < 64; k++)
      acc = fmaf(s_lin1b[d * 65 + k], ng[k], acc);
    out[(long)(b0 + bl) * 64 + d] = fmaxf(acc, 0.0f);
  }
}

extern "C" void kernel_launch(void* const* d_in, const int* in_sizes, int n_in,
                              void* d_out, int out_size) {
  const int*   nodes = (const int*)d_in[0];
  const int*   hui   = (const int*)d_in[1];
  const int*   hr    = (const int*)d_in[2];
  const float* u2e   = (const float*)d_in[3];
  const float* i2e   = (const float*)d_in[4];
  const float* r2e   = (const float*)d_in[5];
  const float* wr1   = (const float*)d_in[6];
  const float* wr1b  = (const float*)d_in[7];
  const float* wr2   = (const float*)d_in[8];
  const float* wr2b  = (const float*)d_in[9];
  const float* att1  = (const float*)d_in[10];
  const float* att1b = (const float*)d_in[11];
  const float* att2  = (const float*)d_in[12];
  const float* att2b = (const float*)d_in[13];
  const float* att3  = (const float*)d_in[14];
  const float* att3b = (const float*)d_in[15];
  const float* lin1  = (const float*)d_in[16];
  const float* lin1b = (const float*)d_in[17];
  float* out = (float*)d_out;

  cudaFuncSetAttribute(ui_aggregator_main_kernel,
                       cudaFuncAttributeMaxDynamicSharedMemorySize, SMEM_BYTES);

  precompute_P_kernel<<<(N_ITEMS + 63) / 64, 256>>>(i2e, wr1);

  ui_aggregator_main_kernel<<<(BB + NB - 1) / NB, NTHR, SMEM_BYTES>>>(
      nodes, hui, hr, u2e, r2e, wr1, wr1b, wr2, wr2b,
      att1, att1b, att2, att2b, att3, att3b, lin1, lin1b, out);
}

// round 3
// speedup vs baseline: 1.5194x; 1.5194x over previous
#include <cuda_runtime.h>

#define BB 16384
#define HH 50
#define DD 64
#define N_ITEMS 100000
#define N_R 5
#define N_PAIRS (N_ITEMS * N_R)
#define NB 5           // batch rows per main CTA
#define NTHR 256
#define TAB_THR 192

// ---------------- persistent device tables ----------------
__device__ float4 g_P[N_ITEMS * 16];      // P[item] = W_r1a @ i2e[item]          (25.6MB)
__device__ float4 g_otab[N_PAIRS * 16];   // o per (item,r)                       (128MB)
__device__ float4 g_a1tab[N_PAIRS * 16];  // att1a @ o per (item,r)               (128MB)
__device__ float  g_uatt[BB * DD];        // att1[:,64:] @ u + att1_b             (4MB)
__device__ float  g_ulin[BB * DD];        // lin1[:,:64] @ u + lin1_b             (4MB)
__device__ float  g_rproj[N_R * DD];      // W_r1b @ r2e[r] + b1

// ---------------- K_P: P = i2e @ W_r1a^T ----------------
__global__ __launch_bounds__(256) void k_P(
    const float* __restrict__ i2e, const float* __restrict__ wr1) {
  __shared__ float e_s[64 * 68];
  __shared__ float wt[64 * 68];   // wt[k*68+d] = wr1[d*128+k]
  const int tid = threadIdx.x;
  const int base = blockIdx.x * 64;
  float* gP = (float*)g_P;

  for (int i = tid; i < 64 * 64; i += 256) {
    int it = i >> 6, k = i & 63;
    int item = base + it;
    e_s[it * 68 + k] = (item < N_ITEMS) ? i2e[(long)item * 64 + k] : 0.0f;
  }
  for (int i = tid; i < 64 * 64; i += 256) {
    int d = i >> 6, k = i & 63;
    wt[k * 68 + d] = wr1[d * 128 + k];
  }
  __syncthreads();

  const int il = tid >> 3;
  const int dq = tid & 7;
  for (int sb = 0; sb < 2; sb++) {
    int it = sb * 32 + il;
    int item = base + it;
    float acc[8];
#pragma unroll
    for (int i = 0; i < 8; i++) acc[i] = 0.0f;
#pragma unroll
    for (int k = 0; k < 64; k++) {
      float ev = e_s[it * 68 + k];
      float4 w0 = *(const float4*)&wt[k * 68 + dq * 8];
      float4 w1 = *(const float4*)&wt[k * 68 + dq * 8 + 4];
      acc[0] = fmaf(ev, w0.x, acc[0]); acc[1] = fmaf(ev, w0.y, acc[1]);
      acc[2] = fmaf(ev, w0.z, acc[2]); acc[3] = fmaf(ev, w0.w, acc[3]);
      acc[4] = fmaf(ev, w1.x, acc[4]); acc[5] = fmaf(ev, w1.y, acc[5]);
      acc[6] = fmaf(ev, w1.z, acc[6]); acc[7] = fmaf(ev, w1.w, acc[7]);
    }
    if (item < N_ITEMS) {
      float4* dst = (float4*)&gP[(long)item * 64 + dq * 8];
      dst[0] = make_float4(acc[0], acc[1], acc[2], acc[3]);
      dst[1] = make_float4(acc[4], acc[5], acc[6], acc[7]);
    }
  }
}

// ---------------- K_R: rproj[r] = W_r1b @ r2e[r] + b1 ----------------
__global__ void k_rproj(const float* __restrict__ wr1,
                        const float* __restrict__ wr1b,
                        const float* __restrict__ r2e) {
  int t = threadIdx.x;
  if (t < N_R * 64) {
    int r = t >> 6, d = t & 63;
    float acc = wr1b[d];
#pragma unroll
    for (int k = 0; k < 64; k++)
      acc = fmaf(wr1[d * 128 + 64 + k], r2e[r * 64 + k], acc);
    g_rproj[r * 64 + d] = acc;
  }
}

// ---------------- K_U: uatt/ulin per batch row ----------------
__global__ __launch_bounds__(256) void k_utab(
    const int* __restrict__ nodes, const float* __restrict__ u2e,
    const float* __restrict__ att1, const float* __restrict__ att1b,
    const float* __restrict__ lin1, const float* __restrict__ lin1b) {
  __shared__ float a_s[64 * 65];   // att1[:,64:]  [d*65+k]
  __shared__ float l_s[64 * 65];   // lin1[:,:64]
  __shared__ float u_s[4 * 64];
  const int t = threadIdx.x;

  for (int i = t; i < 4096; i += 256) {
    int d = i >> 6, k = i & 63;
    a_s[d * 65 + k] = att1[d * 128 + 64 + k];
    l_s[d * 65 + k] = lin1[d * 128 + k];
  }
  const int b0 = blockIdx.x * 64;
  const int bb = t >> 6, d = t & 63;
  for (int it = 0; it < 16; it++) {
    __syncthreads();
    { // stage 4 u rows
      int b = b0 + it * 4 + bb;
      u_s[t] = u2e[(long)nodes[b] * 64 + d];
    }
    __syncthreads();
    const float* uu = &u_s[bb * 64];
    float au = att1b[d], lu = lin1b[d];
#pragma unroll
    for (int k = 0; k < 64; k++) {
      float uv = uu[k];
      au = fmaf(a_s[d * 65 + k], uv, au);
      lu = fmaf(l_s[d * 65 + k], uv, lu);
    }
    int b = b0 + it * 4 + bb;
    g_uatt[b * 64 + d] = au;
    g_ulin[b * 64 + d] = lu;
  }
}

// ---------------- K_TAB: per-(item,r) o and att1a@o ----------------
__global__ __launch_bounds__(TAB_THR, 2) void k_tab(
    const float* __restrict__ wr2, const float* __restrict__ wr2b,
    const float* __restrict__ att1) {
  __shared__ float s_wr2[4096];
  __shared__ float s_a1[4096];
  __shared__ float s_rp[N_R * 68];
  __shared__ float s_b2[64];
  const int t = threadIdx.x;

  for (int i = t; i < 4096; i += TAB_THR) {
    s_wr2[i] = wr2[i];
    int d = i >> 6, k = i & 63;
    s_a1[i] = att1[d * 128 + k];        // att1[:, :64]
  }
  for (int i = t; i < N_R * 64; i += TAB_THR) {
    int r = i >> 6, d = i & 63;
    s_rp[r * 68 + d] = g_rproj[i];
  }
  if (t < 64) s_b2[t] = wr2b[t];
  __syncthreads();

  long row = (long)blockIdx.x * TAB_THR + t;
  if (row >= N_PAIRS) return;
  int item = (int)(row / 5);
  int r = (int)(row - item * 5);

  // h = relu(P[item] + rproj[r])
  float h[64];
  {
    const float4* Pp = &g_P[item * 16];
    const float4* rp = (const float4*)&s_rp[r * 68];
#pragma unroll
    for (int i = 0; i < 16; i++) {
      float4 p = Pp[i];
      float4 q = rp[i];
      h[4 * i + 0] = fmaxf(p.x + q.x, 0.0f);
      h[4 * i + 1] = fmaxf(p.y + q.y, 0.0f);
      h[4 * i + 2] = fmaxf(p.z + q.z, 0.0f);
      h[4 * i + 3] = fmaxf(p.w + q.w, 0.0f);
    }
  }

  // o = relu(W_r2 @ h + b2)  -> regs + gmem
  float o[64];
#pragma unroll
  for (int d0 = 0; d0 < 64; d0 += 8) {
    float acc[8];
#pragma unroll
    for (int i = 0; i < 8; i++) acc[i] = s_b2[d0 + i];
#pragma unroll
    for (int k = 0; k < 64; k += 4) {
#pragma unroll
      for (int i = 0; i < 8; i++) {
        float4 w = *(const float4*)&s_wr2[(d0 + i) * 64 + k];
        acc[i] = fmaf(h[k + 0], w.x, acc[i]);
        acc[i] = fmaf(h[k + 1], w.y, acc[i]);
        acc[i] = fmaf(h[k + 2], w.z, acc[i]);
        acc[i] = fmaf(h[k + 3], w.w, acc[i]);
      }
    }
#pragma unroll
    for (int i = 0; i < 8; i++) o[d0 + i] = fmaxf(acc[i], 0.0f);
  }
  {
    float4* od = &g_otab[row * 16];
#pragma unroll
    for (int i = 0; i < 16; i++)
      od[i] = make_float4(o[4 * i], o[4 * i + 1], o[4 * i + 2], o[4 * i + 3]);
  }

  // a1p = att1a @ o  (no bias/relu; streamed out per 8-block)
  {
    float4* ad = &g_a1tab[row * 16];
#pragma unroll
    for (int d0 = 0; d0 < 64; d0 += 8) {
      float acc[8];
#pragma unroll
      for (int i = 0; i < 8; i++) acc[i] = 0.0f;
#pragma unroll
      for (int k = 0; k < 64; k += 4) {
#pragma unroll
        for (int i = 0; i < 8; i++) {
          float4 w = *(const float4*)&s_a1[(d0 + i) * 64 + k];
          acc[i] = fmaf(o[k + 0], w.x, acc[i]);
          acc[i] = fmaf(o[k + 1], w.y, acc[i]);
          acc[i] = fmaf(o[k + 2], w.z, acc[i]);
          acc[i] = fmaf(o[k + 3], w.w, acc[i]);
        }
      }
      ad[d0 / 4]     = make_float4(acc[0], acc[1], acc[2], acc[3]);
      ad[d0 / 4 + 1] = make_float4(acc[4], acc[5], acc[6], acc[7]);
    }
  }
}

// ---------------- K_MAIN: edges -> logits -> softmax -> aggregate -> out ----------------
__global__ __launch_bounds__(NTHR, 2) void k_main(
    const int* __restrict__ hui, const int* __restrict__ hr,
    const float* __restrict__ att2w, const float* __restrict__ att2b_,
    const float* __restrict__ att3w, const float* __restrict__ att3b_,
    const float* __restrict__ lin1,
    float* __restrict__ out) {
  __shared__ float s_att2[4096];
  __shared__ float s_lin1b[64 * 65];
  __shared__ float s_att3[64], s_a2b[64];
  __shared__ float s_uatt[NB * 64], s_ulin[NB * 64];
  __shared__ float s_logit[NTHR], s_p[NTHR];
  __shared__ int   s_ir[NTHR];
  __shared__ float s_inv[8];
  __shared__ float s_neigh[NB * 64];
  __shared__ float s_a3b;

  const int t = threadIdx.x;
  const int b0 = blockIdx.x * NB;
  const int nb = min(NB, BB - b0);
  const int ne = nb * HH;

  // preamble
  for (int i = t; i < 4096; i += NTHR) {
    s_att2[i] = att2w[i];
    int d = i >> 6, k = i & 63;
    s_lin1b[d * 65 + k] = lin1[d * 128 + 64 + k];
  }
  if (t < 64) { s_att3[t] = att3w[t]; s_a2b[t] = att2b_[t]; }
  if (t == 0) s_a3b = att3b_[0];
  for (int i = t; i < nb * 64; i += NTHR) {
    s_uatt[i] = g_uatt[b0 * 64 + i];
    s_ulin[i] = g_ulin[b0 * 64 + i];
  }
  __syncthreads();

  // edge phase: one edge per thread
  if (t < ne) {
    const int bl = t / HH;
    const int gid = (b0 + bl) * HH + (t - bl * HH);
    const int ir = hui[gid] * 5 + hr[gid];
    s_ir[t] = ir;

    float a1[64];
    {
      const float4* A = &g_a1tab[(long)ir * 16];
      const float* ua = &s_uatt[bl * 64];
#pragma unroll
      for (int i = 0; i < 16; i++) {
        float4 p = A[i];
        a1[4 * i + 0] = fmaxf(p.x + ua[4 * i + 0], 0.0f);
        a1[4 * i + 1] = fmaxf(p.y + ua[4 * i + 1], 0.0f);
        a1[4 * i + 2] = fmaxf(p.z + ua[4 * i + 2], 0.0f);
        a1[4 * i + 3] = fmaxf(p.w + ua[4 * i + 3], 0.0f);
      }
    }
    float lg = s_a3b;
#pragma unroll
    for (int d0 = 0; d0 < 64; d0 += 8) {
      float acc[8];
#pragma unroll
      for (int i = 0; i < 8; i++) acc[i] = s_a2b[d0 + i];
#pragma unroll
      for (int k = 0; k < 64; k += 4) {
#pragma unroll
        for (int i = 0; i < 8; i++) {
          float4 w = *(const float4*)&s_att2[(d0 + i) * 64 + k];
          acc[i] = fmaf(a1[k + 0], w.x, acc[i]);
          acc[i] = fmaf(a1[k + 1], w.y, acc[i]);
          acc[i] = fmaf(a1[k + 2], w.z, acc[i]);
          acc[i] = fmaf(a1[k + 3], w.w, acc[i]);
        }
      }
#pragma unroll
      for (int i = 0; i < 8; i++)
        lg = fmaf(s_att3[d0 + i], fmaxf(acc[i], 0.0f), lg);
    }
    s_logit[t] = lg;
  }
  __syncthreads();

  // softmax: one warp per batch row (HH=50 values)
  {
    const int wid = t >> 5, lane = t & 31;
    if (wid < nb) {
      const float* L = &s_logit[wid * HH];
      float v1 = L[lane];                                  // lane < 32 <= 50
      float v2 = (lane < HH - 32) ? L[32 + lane] : -1e30f;
      float m = fmaxf(v1, v2);
#pragma unroll
      for (int off = 16; off > 0; off >>= 1)
        m = fmaxf(m, __shfl_xor_sync(0xffffffffu, m, off));
      float e1 = __expf(v1 - m);
      float e2 = (lane < HH - 32) ? __expf(v2 - m) : 0.0f;
      s_p[wid * HH + lane] = e1;
      if (lane < HH - 32) s_p[wid * HH + 32 + lane] = e2;
      float s = e1 + e2;
#pragma unroll
      for (int off = 16; off > 0; off >>= 1)
        s += __shfl_xor_sync(0xffffffffu, s, off);
      if (lane == 0) s_inv[wid] = 1.0f / s;
    }
  }
  __syncthreads();

  // neigh[b][d] = (sum_h p * o_tab[ir]) * inv
  const float* otab_f = (const float*)g_otab;
  for (int oi = t; oi < nb * 64; oi += NTHR) {
    int bl = oi >> 6, d = oi & 63;
    const float* pr = &s_p[bl * HH];
    const int* irr = &s_ir[bl * HH];
    float acc = 0.0f;
#pragma unroll 5
    for (int h = 0; h < HH; h++)
      acc = fmaf(pr[h], otab_f[(long)irr[h] * 64 + d], acc);
    s_neigh[oi] = acc * s_inv[bl];
  }
  __syncthreads();

  // out = relu(ulin + lin1[:,64:] @ neigh)
  for (int oi = t; oi < nb * 64; oi += NTHR) {
    int bl = oi >> 6, d = oi & 63;
    float acc = s_ulin[oi];
    const float* ng = &s_neigh[bl * 64];
#pragma unroll
    for (int k = 0; k < 64; k++)
      acc = fmaf(s_lin1b[d * 65 + k], ng[k], acc);
    out[(long)(b0 + bl) * 64 + d] = fmaxf(acc, 0.0f);
  }
}

extern "C" void kernel_launch(void* const* d_in, const int* in_sizes, int n_in,
                              void* d_out, int out_size) {
  const int*   nodes = (const int*)d_in[0];
  const int*   hui   = (const int*)d_in[1];
  const int*   hr    = (const int*)d_in[2];
  const float* u2e   = (const float*)d_in[3];
  const float* i2e   = (const float*)d_in[4];
  const float* r2e   = (const float*)d_in[5];
  const float* wr1   = (const float*)d_in[6];
  const float* wr1b  = (const float*)d_in[7];
  const float* wr2   = (const float*)d_in[8];
  const float* wr2b  = (const float*)d_in[9];
  const float* att1  = (const float*)d_in[10];
  const float* att1b = (const float*)d_in[11];
  const float* att2  = (const float*)d_in[12];
  const float* att2b = (const float*)d_in[13];
  const float* att3  = (const float*)d_in[14];
  const float* att3b = (const float*)d_in[15];
  const float* lin1  = (const float*)d_in[16];
  const float* lin1b = (const float*)d_in[17];
  float* out = (float*)d_out;

  k_P<<<(N_ITEMS + 63) / 64, 256>>>(i2e, wr1);
  k_rproj<<<1, 320>>>(wr1, wr1b, r2e);
  k_utab<<<BB / 64, 256>>>(nodes, u2e, att1, att1b, lin1, lin1b);
  k_tab<<<(N_PAIRS + TAB_THR - 1) / TAB_THR, TAB_THR>>>(wr2, wr2b, att1);
  k_main<<<(BB + NB - 1) / NB, NTHR>>>(hui, hr, att2, att2b, att3, att3b, lin1, out);
}